// round 4
// baseline (speedup 1.0000x reference)
#include <cuda_runtime.h>
#include <math.h>

#define NFRAMES 480          // B(16) * STEPS(30)
#define KDIM    5625         // 75*75 pooled cells
#define NNEUR   54
#define NPAD    64
#define STEPS   30
#define BATCH   16
#define FT      8            // frames per fused block
#define CROWS   5            // pooled rows per chunk
#define CCELLS  (CROWS * 75) // 375 cells per chunk
#define NCHUNK  15           // 75 / CROWS

// -------- scratch (device globals; no allocation allowed) --------
__device__ float g_wT[KDIM * NPAD];                     // transposed padded weights ~1.44 MB
__device__ float g_partial[NCHUNK * NFRAMES * NNEUR];   // split-K partials
__device__ float g_frames[NFRAMES * NNEUR];             // merged FC outputs

// ================= 1) transpose weights: fc_w[54][5625] -> wT[5625][64] (zero-pad) =====
__global__ void wT_kernel(const float* __restrict__ fc_w) {
    int i = blockIdx.x * blockDim.x + threadIdx.x;
    if (i >= KDIM * NPAD) return;
    int k = i >> 6;
    int n = i & 63;
    g_wT[i] = (n < NNEUR) ? fc_w[n * KDIM + k] : 0.f;
}

// ================= 2) fused pool(8x8 avg) + FC, split-K over pooled-row chunks =========
// grid (NFRAMES/FT = 60, NCHUNK = 15), 256 threads.
__global__ void fused_kernel(const float* __restrict__ x) {
    __shared__ float xp_s[FT * CCELLS];        // 12000 B
    __shared__ float red[4 * FT * NPAD];       //  8192 B

    const int tid = threadIdx.x;
    const int f0  = blockIdx.x * FT;
    const int pr0 = blockIdx.y * CROWS;
    const int k0  = blockIdx.y * CCELLS;       // global pooled-cell base

    // ---- stage 1: pooling. each iteration computes one pooled cell (64 input floats)
    for (int idx = tid; idx < FT * CCELLS; idx += 256) {
        int f  = idx / CCELLS;
        int c  = idx - f * CCELLS;
        int pr = c / 75;
        int pc = c - pr * 75;
        const float* p = x + ((size_t)(f0 + f) * 600 + (size_t)(pr0 + pr) * 8) * 600 + pc * 8;
        float s = 0.f;
#pragma unroll
        for (int r = 0; r < 8; r++) {
            float4 a = *(const float4*)(p + (size_t)r * 600);
            float4 b = *(const float4*)(p + (size_t)r * 600 + 4);
            s += ((a.x + a.y) + (a.z + a.w)) + ((b.x + b.y) + (b.z + b.w));
        }
        xp_s[idx] = s * (1.f / 64.f);
    }
    __syncthreads();

    // ---- stage 2: FC. n = tid&63, k-group g = tid>>6 (4 groups over the 375 cells)
    const int n = tid & 63;
    const int g = tid >> 6;
    float acc[FT];
#pragma unroll
    for (int f = 0; f < FT; f++) acc[f] = 0.f;

    for (int p = g; p < CCELLS; p += 4) {
        float w = g_wT[(size_t)(k0 + p) * NPAD + n];   // warp-coalesced 128B, L2-resident
#pragma unroll
        for (int f = 0; f < FT; f++)
            acc[f] += xp_s[f * CCELLS + p] * w;        // smem broadcast across n
    }
#pragma unroll
    for (int f = 0; f < FT; f++)
        red[(g * FT + f) * NPAD + n] = acc[f];
    __syncthreads();

    // ---- stage 3: fixed-order reduction over 4 k-groups, write split-K partial
    for (int idx = tid; idx < FT * NPAD; idx += 256) {
        int f = idx >> 6;
        int nn = idx & 63;
        float s = ((red[(0 * FT + f) * NPAD + nn]  + red[(1 * FT + f) * NPAD + nn])
                +  (red[(2 * FT + f) * NPAD + nn]  + red[(3 * FT + f) * NPAD + nn]));
        if (nn < NNEUR)
            g_partial[((size_t)blockIdx.y * NFRAMES + (f0 + f)) * NNEUR + nn] = s;
    }
}

// ================= 3) merge partials + bias (fixed order => deterministic) =============
__global__ void merge_kernel(const float* __restrict__ fc_b) {
    int i = blockIdx.x * blockDim.x + threadIdx.x;
    if (i >= NFRAMES * NNEUR) return;
    int n = i % NNEUR;
    float s = fc_b[n];
#pragma unroll
    for (int c = 0; c < NCHUNK; c++)
        s += g_partial[(size_t)c * (NFRAMES * NNEUR) + i];
    g_frames[i] = s;
}

// ================= 4) spike scan: 1024 threads = 16 batches x 64 (padded neurons) ======
// 2 barriers per step. Per-batch lateral = warp butterfly + 2 smem reads (batch = 2
// warps). Global mean = warp butterfly + every thread sums 32 warp-sums (fixed order).
__global__ void scan_kernel(const float* __restrict__ lw, const float* __restrict__ hw,
                            float* __restrict__ out) {
    __shared__ __align__(16) float wh[32];   // per-warp hsum sums
    __shared__ __align__(16) float wr[32];   // per-warp rate sums

    const int tid  = threadIdx.x;            // 0..1023
    const int b    = tid >> 6;               // batch
    const int n    = tid & 63;               // padded neuron
    const int wid  = tid >> 5;
    const int lane = tid & 31;
    const bool act = (n < NNEUR);

    float w0 = hw[0], w1 = hw[1], w2 = hw[2], w3 = hw[3];
    float l0 = 0.f, l1 = 0.f, l2 = 0.f, l3 = 0.f;
    if (act) { l0 = lw[n*4+0]; l1 = lw[n*4+1]; l2 = lw[n*4+2]; l3 = lw[n*4+3]; }
    float h0 = 0.f, h1 = 0.f, h2 = 0.f, h3 = 0.f, count = 0.f;

    for (int t = 0; t < STEPS; t++) {
        float frame = act ? g_frames[(b * STEPS + t) * NNEUR + n] : 0.f;
        float hsum = h0 * l0 + h1 * l1 + h2 * l2 + h3 * l3;   // 0 for inactive
        float hh   = h0 * w0 + h1 * w1 + h2 * w2 + h3 * w3;

        // warp butterfly of hsum
        float v = hsum;
        v += __shfl_xor_sync(0xffffffffu, v, 16);
        v += __shfl_xor_sync(0xffffffffu, v, 8);
        v += __shfl_xor_sync(0xffffffffu, v, 4);
        v += __shfl_xor_sync(0xffffffffu, v, 2);
        v += __shfl_xor_sync(0xffffffffu, v, 1);
        if (lane == 0) wh[wid] = v;
        __syncthreads();                                      // bar1

        float bsum = wh[2 * b] + wh[2 * b + 1];
        float rate = act ? expf(frame + (bsum - hsum) + hh) : 0.f;

        // warp butterfly of rate
        float r = rate;
        r += __shfl_xor_sync(0xffffffffu, r, 16);
        r += __shfl_xor_sync(0xffffffffu, r, 8);
        r += __shfl_xor_sync(0xffffffffu, r, 4);
        r += __shfl_xor_sync(0xffffffffu, r, 2);
        r += __shfl_xor_sync(0xffffffffu, r, 1);
        if (lane == 0) wr[wid] = r;
        __syncthreads();                                      // bar2

        // every thread sums the 32 warp sums in identical fixed order
        const float4* w4 = (const float4*)wr;
        float tot = 0.f;
#pragma unroll
        for (int i = 0; i < 8; i++) {
            float4 q = w4[i];
            tot += (q.x + q.y) + (q.z + q.w);
        }
        float thr = tot * (1.f / (BATCH * NNEUR));

        float s = (act && rate > thr) ? 1.f : 0.f;
        count += s;
        h0 = h1; h1 = h2; h2 = h3; h3 = s;
        // NOTE: next iteration's wh write is ordered after this iteration's wr reads
        // by bar1(t+1); wr(t+1) write is ordered after wr(t) reads by bar1(t+1) too.
    }
    if (act)
        out[b * NNEUR + n] = count + log1pf(expf(-count));    // exact softplus, count>=0
}

// =======================================================================================
extern "C" void kernel_launch(void* const* d_in, const int* in_sizes, int n_in,
                              void* d_out, int out_size) {
    const float* x    = (const float*)d_in[0];
    const float* fc_w = (const float*)d_in[1];
    const float* fc_b = (const float*)d_in[2];
    const float* lw   = (const float*)d_in[3];
    const float* hw   = (const float*)d_in[4];
    float* out = (float*)d_out;

    wT_kernel<<<(KDIM * NPAD + 255) / 256, 256>>>(fc_w);
    fused_kernel<<<dim3(NFRAMES / FT, NCHUNK), 256>>>(x);
    merge_kernel<<<(NFRAMES * NNEUR + 255) / 256, 256>>>(fc_b);
    scan_kernel<<<1, 1024>>>(lw, hw, out);
    (void)in_sizes; (void)n_in; (void)out_size;
}

// round 5
// speedup vs baseline: 1.0647x; 1.0647x over previous
#include <cuda_runtime.h>
#include <math.h>

#define NFRAMES 480          // B(16) * STEPS(30)
#define KDIM    5625         // 75*75 pooled cells
#define NNEUR   54
#define NPAD    64
#define STEPS   30
#define BATCH   16
#define FT      8            // frames per fused block
#define CROWS   5            // pooled rows per chunk
#define NCHUNK  15           // 75 / CROWS

// -------- scratch (device globals; no allocation allowed) --------
__device__ float g_wT[KDIM * NPAD];                     // transposed padded weights ~1.44 MB
__device__ float g_partial[NCHUNK * NFRAMES * NNEUR];   // split-K partials
__device__ float g_frames[NFRAMES * NNEUR];             // merged FC outputs

// ================= 1) transpose weights: fc_w[54][5625] -> wT[5625][64] (zero-pad) =====
__global__ void wT_kernel(const float* __restrict__ fc_w) {
    int i = blockIdx.x * blockDim.x + threadIdx.x;
    if (i >= KDIM * NPAD) return;
    int k = i >> 6;
    int n = i & 63;
    g_wT[i] = (n < NNEUR) ? fc_w[n * KDIM + k] : 0.f;
}

// ================= 2) fused pool(8x8) + FC, row-pipelined (double-buffered smem) =======
// grid (60, 15), 256 threads. Per chunk: 5 pooled rows. Pool row r+1 while FC'ing row r.
__global__ void fused_kernel(const float* __restrict__ x) {
    __shared__ float xp_s[2][FT * 75];         // 2 x 2400 B
    __shared__ float red[4 * FT * NPAD];       // 8192 B

    const int tid = threadIdx.x;
    const int f0  = blockIdx.x * FT;
    const int pr0 = blockIdx.y * CROWS;

    auto pool_row = [&](int r, int buf) {
        const int prg = pr0 + r;
        for (int idx = tid; idx < FT * 75; idx += 256) {
            int f  = idx / 75;
            int pc = idx - f * 75;
            const float* p = x + ((size_t)(f0 + f) * 600 + (size_t)prg * 8) * 600 + pc * 8;
            float s = 0.f;
#pragma unroll
            for (int rr = 0; rr < 8; rr++) {
                float4 a = *(const float4*)(p + (size_t)rr * 600);
                float4 b = *(const float4*)(p + (size_t)rr * 600 + 4);
                s += ((a.x + a.y) + (a.z + a.w)) + ((b.x + b.y) + (b.z + b.w));
            }
            xp_s[buf][idx] = s * (1.f / 64.f);
        }
    };

    const int n = tid & 63;
    const int g = tid >> 6;
    float acc[FT];
#pragma unroll
    for (int f = 0; f < FT; f++) acc[f] = 0.f;

    pool_row(0, 0);
    __syncthreads();
    for (int r = 0; r < CROWS; r++) {
        if (r + 1 < CROWS) pool_row(r + 1, (r + 1) & 1);   // issues next row's LDGs
        const int kbase = (pr0 + r) * 75;                   // global pooled-cell index base
        const float* buf = xp_s[r & 1];
        for (int p = g; p < 75; p += 4) {
            float w = g_wT[(size_t)(kbase + p) * NPAD + n]; // coalesced, L2-resident
#pragma unroll
            for (int f = 0; f < FT; f++)
                acc[f] += buf[f * 75 + p] * w;              // smem broadcast across n
        }
        __syncthreads();   // pool(r+1) done + FC(r) reads done before buf reuse
    }

#pragma unroll
    for (int f = 0; f < FT; f++)
        red[(g * FT + f) * NPAD + n] = acc[f];
    __syncthreads();

    // fixed-order reduction over 4 k-groups, write split-K partial
    for (int idx = tid; idx < FT * NPAD; idx += 256) {
        int f  = idx >> 6;
        int nn = idx & 63;
        float s = ((red[(0 * FT + f) * NPAD + nn] + red[(1 * FT + f) * NPAD + nn])
                +  (red[(2 * FT + f) * NPAD + nn] + red[(3 * FT + f) * NPAD + nn]));
        if (nn < NNEUR)
            g_partial[((size_t)blockIdx.y * NFRAMES + (f0 + f)) * NNEUR + nn] = s;
    }
}

// ================= 3) merge partials + bias (fixed order => deterministic) =============
__global__ void merge_kernel(const float* __restrict__ fc_b) {
    int i = blockIdx.x * blockDim.x + threadIdx.x;
    if (i >= NFRAMES * NNEUR) return;
    int n = i % NNEUR;
    float s = fc_b[n];
#pragma unroll
    for (int c = 0; c < NCHUNK; c++)
        s += g_partial[(size_t)c * (NFRAMES * NNEUR) + i];
    g_frames[i] = s;
}

// ================= 4) spike scan: 512 threads = 16 warps, 1 warp per batch =============
// Each lane owns 2 neuron slots (n=lane, n=lane+32). Per-batch lateral sum = one warp
// butterfly (no smem). Global rate mean = butterfly + wr[2][16] + ONE barrier per step
// (double-buffered -> race-free). All 30 frames preloaded into registers.
__global__ void scan_kernel(const float* __restrict__ lw, const float* __restrict__ hw,
                            float* __restrict__ out) {
    __shared__ __align__(16) float wr[2][16];

    const int tid  = threadIdx.x;            // 0..511
    const int b    = tid >> 5;               // batch == warp id
    const int lane = tid & 31;
    const bool actb = (lane < NNEUR - 32);   // slot B active: lane+32 < 54

    // preload frames (MLP ~60, once)
    float fra[STEPS], frb[STEPS];
#pragma unroll
    for (int t = 0; t < STEPS; t++) {
        const float* row = g_frames + (b * STEPS + t) * NNEUR;
        fra[t] = row[lane];
        frb[t] = actb ? row[lane + 32] : 0.f;
    }

    const float w0 = hw[0], w1 = hw[1], w2 = hw[2], w3 = hw[3];
    const float la0 = lw[lane*4+0], la1 = lw[lane*4+1], la2 = lw[lane*4+2], la3 = lw[lane*4+3];
    float lb0 = 0.f, lb1 = 0.f, lb2 = 0.f, lb3 = 0.f;
    if (actb) { lb0 = lw[(lane+32)*4+0]; lb1 = lw[(lane+32)*4+1];
                lb2 = lw[(lane+32)*4+2]; lb3 = lw[(lane+32)*4+3]; }

    float a0=0.f,a1=0.f,a2=0.f,a3=0.f, b0=0.f,b1=0.f,b2=0.f,b3=0.f;
    float cnta = 0.f, cntb = 0.f;

    for (int t = 0; t < STEPS; t++) {
        float hsa = a0*la0 + a1*la1 + a2*la2 + a3*la3;
        float hsb = b0*lb0 + b1*lb1 + b2*lb2 + b3*lb3;   // 0 for inactive
        float hha = a0*w0 + a1*w1 + a2*w2 + a3*w3;
        float hhb = b0*w0 + b1*w1 + b2*w2 + b3*w3;

        // per-batch lateral sum: single warp butterfly
        float v = hsa + hsb;
        v += __shfl_xor_sync(0xffffffffu, v, 16);
        v += __shfl_xor_sync(0xffffffffu, v, 8);
        v += __shfl_xor_sync(0xffffffffu, v, 4);
        v += __shfl_xor_sync(0xffffffffu, v, 2);
        v += __shfl_xor_sync(0xffffffffu, v, 1);
        // v == bsum (all lanes)

        float ra = expf(fra[t] + (v - hsa) + hha);
        float rb = actb ? expf(frb[t] + (v - hsb) + hhb) : 0.f;

        // global rate sum
        float r = ra + rb;
        r += __shfl_xor_sync(0xffffffffu, r, 16);
        r += __shfl_xor_sync(0xffffffffu, r, 8);
        r += __shfl_xor_sync(0xffffffffu, r, 4);
        r += __shfl_xor_sync(0xffffffffu, r, 2);
        r += __shfl_xor_sync(0xffffffffu, r, 1);
        if (lane == 0) wr[t & 1][b] = r;
        __syncthreads();                                  // the only barrier per step

        const float4* w4 = (const float4*)wr[t & 1];
        float4 q0 = w4[0], q1 = w4[1], q2 = w4[2], q3 = w4[3];
        float tot = ((q0.x + q0.y) + (q0.z + q0.w)) + ((q1.x + q1.y) + (q1.z + q1.w))
                  + ((q2.x + q2.y) + (q2.z + q2.w)) + ((q3.x + q3.y) + (q3.z + q3.w));
        float thr = tot * (1.f / (BATCH * NNEUR));

        float sa = (ra > thr) ? 1.f : 0.f;
        float sb = (rb > thr) ? 1.f : 0.f;                // rb==0 for inactive -> 0
        cnta += sa;  cntb += sb;
        a0 = a1; a1 = a2; a2 = a3; a3 = sa;
        b0 = b1; b1 = b2; b2 = b3; b3 = sb;
        // wr[t&1] is overwritten at t+2, after bar(t+1) which follows all reads at t.
    }
    out[b * NNEUR + lane] = cnta + log1pf(expf(-cnta));
    if (actb)
        out[b * NNEUR + lane + 32] = cntb + log1pf(expf(-cntb));
}

// =======================================================================================
extern "C" void kernel_launch(void* const* d_in, const int* in_sizes, int n_in,
                              void* d_out, int out_size) {
    const float* x    = (const float*)d_in[0];
    const float* fc_w = (const float*)d_in[1];
    const float* fc_b = (const float*)d_in[2];
    const float* lw   = (const float*)d_in[3];
    const float* hw   = (const float*)d_in[4];
    float* out = (float*)d_out;

    wT_kernel<<<(KDIM * NPAD + 255) / 256, 256>>>(fc_w);
    fused_kernel<<<dim3(NFRAMES / FT, NCHUNK), 256>>>(x);
    merge_kernel<<<(NFRAMES * NNEUR + 255) / 256, 256>>>(fc_b);
    scan_kernel<<<1, 512>>>(lw, hw, out);
    (void)in_sizes; (void)n_in; (void)out_size;
}

// round 6
// speedup vs baseline: 1.1137x; 1.0460x over previous
#include <cuda_runtime.h>
#include <math.h>

#define NFRAMES 480          // B(16) * STEPS(30)
#define KDIM    5625         // 75*75 pooled cells
#define NNEUR   54
#define NPAD    64
#define STEPS   30
#define BATCH   16
#define FT      8            // frames per fused block
#define CROWS   5            // pooled rows per chunk
#define CCELLS  (CROWS * 75) // 375 cells per chunk
#define NCHUNK  15           // 75 / CROWS

// -------- scratch (device globals; no allocation allowed) --------
__device__ float g_wT[KDIM * NPAD];                     // transposed padded weights ~1.44 MB
__device__ float g_partial[NCHUNK * NFRAMES * NNEUR];   // split-K partials
__device__ float g_frames[NFRAMES * NNEUR];             // merged FC outputs

// ================= 1) transpose weights: fc_w[54][5625] -> wT[5625][64] (zero-pad) =====
__global__ void wT_kernel(const float* __restrict__ fc_w) {
    int i = blockIdx.x * blockDim.x + threadIdx.x;
    if (i >= KDIM * NPAD) return;
    int k = i >> 6;
    int n = i & 63;
    g_wT[i] = (n < NNEUR) ? fc_w[n * KDIM + k] : 0.f;
}

// ================= 2) fused pool(8x8 avg) + FC (R2 structure — best measured) ==========
// grid (60, 15), 256 threads. One big pool phase (high MLP), then FC from smem.
__global__ void fused_kernel(const float* __restrict__ x) {
    __shared__ float xp_s[FT * CCELLS];        // 12000 B
    __shared__ float red[4 * FT * NPAD];       //  8192 B

    const int tid = threadIdx.x;
    const int f0  = blockIdx.x * FT;
    const int pr0 = blockIdx.y * CROWS;
    const int k0  = blockIdx.y * CCELLS;       // global pooled-cell base

    // ---- stage 1: pooling. each iteration computes one pooled cell (64 input floats)
    for (int idx = tid; idx < FT * CCELLS; idx += 256) {
        int f  = idx / CCELLS;
        int c  = idx - f * CCELLS;
        int pr = c / 75;
        int pc = c - pr * 75;
        const float* p = x + ((size_t)(f0 + f) * 600 + (size_t)(pr0 + pr) * 8) * 600 + pc * 8;
        float s = 0.f;
#pragma unroll
        for (int r = 0; r < 8; r++) {
            float4 a = *(const float4*)(p + (size_t)r * 600);
            float4 b = *(const float4*)(p + (size_t)r * 600 + 4);
            s += ((a.x + a.y) + (a.z + a.w)) + ((b.x + b.y) + (b.z + b.w));
        }
        xp_s[idx] = s * (1.f / 64.f);
    }
    __syncthreads();

    // ---- stage 2: FC. n = tid&63, k-group g = tid>>6 (4 groups over the 375 cells)
    const int n = tid & 63;
    const int g = tid >> 6;
    float acc[FT];
#pragma unroll
    for (int f = 0; f < FT; f++) acc[f] = 0.f;

    for (int p = g; p < CCELLS; p += 4) {
        float w = g_wT[(size_t)(k0 + p) * NPAD + n];   // warp-coalesced 128B, L2-resident
#pragma unroll
        for (int f = 0; f < FT; f++)
            acc[f] += xp_s[f * CCELLS + p] * w;        // smem broadcast across n
    }
#pragma unroll
    for (int f = 0; f < FT; f++)
        red[(g * FT + f) * NPAD + n] = acc[f];
    __syncthreads();

    // ---- stage 3: fixed-order reduction over 4 k-groups, write split-K partial
    for (int idx = tid; idx < FT * NPAD; idx += 256) {
        int f  = idx >> 6;
        int nn = idx & 63;
        float s = ((red[(0 * FT + f) * NPAD + nn] + red[(1 * FT + f) * NPAD + nn])
                +  (red[(2 * FT + f) * NPAD + nn] + red[(3 * FT + f) * NPAD + nn]));
        if (nn < NNEUR)
            g_partial[((size_t)blockIdx.y * NFRAMES + (f0 + f)) * NNEUR + nn] = s;
    }
}

// ================= 3) merge partials + bias (fixed order => deterministic) =============
__global__ void merge_kernel(const float* __restrict__ fc_b) {
    int i = blockIdx.x * blockDim.x + threadIdx.x;
    if (i >= NFRAMES * NNEUR) return;
    int n = i % NNEUR;
    float s = fc_b[n];
#pragma unroll
    for (int c = 0; c < NCHUNK; c++)
        s += g_partial[(size_t)c * (NFRAMES * NNEUR) + i];
    g_frames[i] = s;
}

// ================= 4) spike scan: 512 threads = 16 warps, 1 warp per batch =============
// rate = exp(frame - hsum + hh) * exp(bsum): per-thread factor e needs no reduction, so
// the hsum-butterfly and e-sum-butterfly are independent and interleave. One barrier per
// step (double-buffered wr). Main loop fully unrolled so frame preloads stay in regs.
__global__ void __launch_bounds__(512) scan_kernel(
        const float* __restrict__ lw, const float* __restrict__ hw,
        float* __restrict__ out) {
    __shared__ __align__(16) float wr[2][16];

    const int tid  = threadIdx.x;            // 0..511
    const int b    = tid >> 5;               // batch == warp id
    const int lane = tid & 31;
    const bool actb = (lane < NNEUR - 32);   // slot B active: lane+32 < 54

    // preload all frames into registers (loop fully unrolled below)
    float fra[STEPS], frb[STEPS];
#pragma unroll
    for (int t = 0; t < STEPS; t++) {
        const float* row = g_frames + (b * STEPS + t) * NNEUR;
        fra[t] = row[lane];
        frb[t] = actb ? row[lane + 32] : 0.f;
    }

    const float w0 = hw[0], w1 = hw[1], w2 = hw[2], w3 = hw[3];
    const float la0 = lw[lane*4+0], la1 = lw[lane*4+1], la2 = lw[lane*4+2], la3 = lw[lane*4+3];
    float lb0 = 0.f, lb1 = 0.f, lb2 = 0.f, lb3 = 0.f;
    if (actb) { lb0 = lw[(lane+32)*4+0]; lb1 = lw[(lane+32)*4+1];
                lb2 = lw[(lane+32)*4+2]; lb3 = lw[(lane+32)*4+3]; }

    float a0=0.f,a1=0.f,a2=0.f,a3=0.f, b0=0.f,b1=0.f,b2=0.f,b3=0.f;
    float cnta = 0.f, cntb = 0.f;

#pragma unroll
    for (int t = 0; t < STEPS; t++) {
        float hsa = a0*la0 + a1*la1 + a2*la2 + a3*la3;
        float hsb = b0*lb0 + b1*lb1 + b2*lb2 + b3*lb3;   // 0 for inactive
        float hha = a0*w0 + a1*w1 + a2*w2 + a3*w3;
        float hhb = b0*w0 + b1*w1 + b2*w2 + b3*w3;

        float ea = expf(fra[t] - hsa + hha);             // no reduction dependency
        float eb = actb ? expf(frb[t] - hsb + hhb) : 0.f;

        // two INDEPENDENT interleaved butterflies: v -> bsum, s -> sum of e
        float v = hsa + hsb;
        float s = ea + eb;
        v += __shfl_xor_sync(0xffffffffu, v, 16);  s += __shfl_xor_sync(0xffffffffu, s, 16);
        v += __shfl_xor_sync(0xffffffffu, v, 8);   s += __shfl_xor_sync(0xffffffffu, s, 8);
        v += __shfl_xor_sync(0xffffffffu, v, 4);   s += __shfl_xor_sync(0xffffffffu, s, 4);
        v += __shfl_xor_sync(0xffffffffu, v, 2);   s += __shfl_xor_sync(0xffffffffu, s, 2);
        v += __shfl_xor_sync(0xffffffffu, v, 1);   s += __shfl_xor_sync(0xffffffffu, s, 1);

        float ebb = expf(v);                             // exp(bsum), all lanes
        if (lane == 0) wr[t & 1][b] = ebb * s;           // batch rate sum
        __syncthreads();                                 // the only barrier per step

        const float4* w4 = (const float4*)wr[t & 1];
        float4 q0 = w4[0], q1 = w4[1], q2 = w4[2], q3 = w4[3];
        float tot = (((q0.x + q0.y) + (q0.z + q0.w)) + ((q1.x + q1.y) + (q1.z + q1.w)))
                  + (((q2.x + q2.y) + (q2.z + q2.w)) + ((q3.x + q3.y) + (q3.z + q3.w)));
        float thr = tot * (1.f / (BATCH * NNEUR));

        float sa = (ea * ebb > thr) ? 1.f : 0.f;
        float sb = (eb * ebb > thr) ? 1.f : 0.f;         // eb==0 -> never spikes (thr>0)
        cnta += sa;  cntb += sb;
        a0 = a1; a1 = a2; a2 = a3; a3 = sa;
        b0 = b1; b1 = b2; b2 = b3; b3 = sb;
    }
    out[b * NNEUR + lane] = cnta + log1pf(expf(-cnta));  // exact softplus, count>=0
    if (actb)
        out[b * NNEUR + lane + 32] = cntb + log1pf(expf(-cntb));
}

// =======================================================================================
extern "C" void kernel_launch(void* const* d_in, const int* in_sizes, int n_in,
                              void* d_out, int out_size) {
    const float* x    = (const float*)d_in[0];
    const float* fc_w = (const float*)d_in[1];
    const float* fc_b = (const float*)d_in[2];
    const float* lw   = (const float*)d_in[3];
    const float* hw   = (const float*)d_in[4];
    float* out = (float*)d_out;

    wT_kernel<<<(KDIM * NPAD + 255) / 256, 256>>>(fc_w);
    fused_kernel<<<dim3(NFRAMES / FT, NCHUNK), 256>>>(x);
    merge_kernel<<<(NFRAMES * NNEUR + 255) / 256, 256>>>(fc_b);
    scan_kernel<<<1, 512>>>(lw, hw, out);
    (void)in_sizes; (void)n_in; (void)out_size;
}

// round 7
// speedup vs baseline: 1.2004x; 1.0778x over previous
#include <cuda_runtime.h>
#include <math.h>

#define NFRAMES 480          // B(16) * STEPS(30)
#define KDIM    5625         // 75*75 pooled cells
#define NNEUR   54
#define NPAD    64
#define STEPS   30
#define BATCH   16
#define FT      8            // frames per fused block
#define CROWS   5            // pooled rows per chunk
#define CCELLS  (CROWS * 75) // 375 cells per chunk
#define NCHUNK  15           // 75 / CROWS

// -------- scratch (device globals; no allocation allowed) --------
__device__ float g_wT[KDIM * NPAD];                     // transposed padded weights ~1.44 MB
__device__ float g_partial[NCHUNK * NFRAMES * NNEUR];   // split-K partials
__device__ float g_frames[NFRAMES * NNEUR];             // merged FC outputs

// ================= 1) transpose weights: fc_w[54][5625] -> wT[5625][64] (zero-pad) =====
__global__ void wT_kernel(const float* __restrict__ fc_w) {
    int i = blockIdx.x * blockDim.x + threadIdx.x;
    if (i >= KDIM * NPAD) return;
    int k = i >> 6;
    int n = i & 63;
    g_wT[i] = (n < NNEUR) ? fc_w[n * KDIM + k] : 0.f;
}

// ================= 2) fused pool(8x8 avg) + FC =========================================
// grid (60, 15), 256 threads. Pool phase: big batched __ldcs LDG stream (evict-first so
// the wT tile stays L2-resident). smem tile stored f-MINOR (xp_s[c*FT+f]) so the FC
// phase reads 8 frame values with 2 LDS.128 (broadcast) instead of 8 scalar LDS.
__global__ void fused_kernel(const float* __restrict__ x) {
    __shared__ __align__(16) float xp_s[CCELLS * FT];  // 12000 B, [cell][frame]
    __shared__ float red[4 * FT * NPAD];               //  8192 B

    const int tid = threadIdx.x;
    const int f0  = blockIdx.x * FT;
    const int pr0 = blockIdx.y * CROWS;
    const int k0  = blockIdx.y * CCELLS;       // global pooled-cell base

    // ---- stage 1: pooling. one pooled cell (64 input floats) per iteration
    for (int idx = tid; idx < FT * CCELLS; idx += 256) {
        int f  = idx / CCELLS;
        int c  = idx - f * CCELLS;
        int pr = c / 75;
        int pc = c - pr * 75;
        const float* p = x + ((size_t)(f0 + f) * 600 + (size_t)(pr0 + pr) * 8) * 600 + pc * 8;
        float s = 0.f;
#pragma unroll
        for (int r = 0; r < 8; r++) {
            float4 a = __ldcs((const float4*)(p + (size_t)r * 600));
            float4 b = __ldcs((const float4*)(p + (size_t)r * 600 + 4));
            s += ((a.x + a.y) + (a.z + a.w)) + ((b.x + b.y) + (b.z + b.w));
        }
        xp_s[c * FT + f] = s * (1.f / 64.f);   // f-minor store (4-way bank conflict, rare)
    }
    __syncthreads();

    // ---- stage 2: FC. n = tid&63, k-group g = tid>>6 (4 groups over the 375 cells)
    const int n = tid & 63;
    const int g = tid >> 6;
    float acc[FT];
#pragma unroll
    for (int f = 0; f < FT; f++) acc[f] = 0.f;

    for (int p = g; p < CCELLS; p += 4) {
        float w = g_wT[(size_t)(k0 + p) * NPAD + n];       // coalesced 128B, L2-resident
        float4 xa = *(const float4*)&xp_s[p * FT];         // LDS.128 broadcast
        float4 xb = *(const float4*)&xp_s[p * FT + 4];
        acc[0] += xa.x * w;  acc[1] += xa.y * w;
        acc[2] += xa.z * w;  acc[3] += xa.w * w;
        acc[4] += xb.x * w;  acc[5] += xb.y * w;
        acc[6] += xb.z * w;  acc[7] += xb.w * w;
    }
#pragma unroll
    for (int f = 0; f < FT; f++)
        red[(g * FT + f) * NPAD + n] = acc[f];
    __syncthreads();

    // ---- stage 3: fixed-order reduction over 4 k-groups, write split-K partial
    for (int idx = tid; idx < FT * NPAD; idx += 256) {
        int f  = idx >> 6;
        int nn = idx & 63;
        float s = ((red[(0 * FT + f) * NPAD + nn] + red[(1 * FT + f) * NPAD + nn])
                +  (red[(2 * FT + f) * NPAD + nn] + red[(3 * FT + f) * NPAD + nn]));
        if (nn < NNEUR)
            g_partial[((size_t)blockIdx.y * NFRAMES + (f0 + f)) * NNEUR + nn] = s;
    }
}

// ================= 3) merge partials + bias (fixed order => deterministic) =============
__global__ void merge_kernel(const float* __restrict__ fc_b) {
    int i = blockIdx.x * blockDim.x + threadIdx.x;
    if (i >= NFRAMES * NNEUR) return;
    int n = i % NNEUR;
    float s = fc_b[n];
#pragma unroll
    for (int c = 0; c < NCHUNK; c++)
        s += g_partial[(size_t)c * (NFRAMES * NNEUR) + i];
    g_frames[i] = s;
}

// ================= 4) spike scan: 512 threads = 16 warps, 1 warp per batch =============
// rate = exp(frame - hsum + hh) * exp(bsum): per-thread factor e needs no reduction, so
// the hsum-butterfly and e-sum-butterfly are independent and interleave. One barrier per
// step (double-buffered wr). Main loop fully unrolled so frame preloads stay in regs.
__global__ void __launch_bounds__(512) scan_kernel(
        const float* __restrict__ lw, const float* __restrict__ hw,
        float* __restrict__ out) {
    __shared__ __align__(16) float wr[2][16];

    const int tid  = threadIdx.x;            // 0..511
    const int b    = tid >> 5;               // batch == warp id
    const int lane = tid & 31;
    const bool actb = (lane < NNEUR - 32);   // slot B active: lane+32 < 54

    // preload all frames into registers (loop fully unrolled below)
    float fra[STEPS], frb[STEPS];
#pragma unroll
    for (int t = 0; t < STEPS; t++) {
        const float* row = g_frames + (b * STEPS + t) * NNEUR;
        fra[t] = row[lane];
        frb[t] = actb ? row[lane + 32] : 0.f;
    }

    const float w0 = hw[0], w1 = hw[1], w2 = hw[2], w3 = hw[3];
    const float la0 = lw[lane*4+0], la1 = lw[lane*4+1], la2 = lw[lane*4+2], la3 = lw[lane*4+3];
    float lb0 = 0.f, lb1 = 0.f, lb2 = 0.f, lb3 = 0.f;
    if (actb) { lb0 = lw[(lane+32)*4+0]; lb1 = lw[(lane+32)*4+1];
                lb2 = lw[(lane+32)*4+2]; lb3 = lw[(lane+32)*4+3]; }

    float a0=0.f,a1=0.f,a2=0.f,a3=0.f, b0=0.f,b1=0.f,b2=0.f,b3=0.f;
    float cnta = 0.f, cntb = 0.f;

#pragma unroll
    for (int t = 0; t < STEPS; t++) {
        float hsa = a0*la0 + a1*la1 + a2*la2 + a3*la3;
        float hsb = b0*lb0 + b1*lb1 + b2*lb2 + b3*lb3;   // 0 for inactive
        float hha = a0*w0 + a1*w1 + a2*w2 + a3*w3;
        float hhb = b0*w0 + b1*w1 + b2*w2 + b3*w3;

        float ea = expf(fra[t] - hsa + hha);             // no reduction dependency
        float eb = actb ? expf(frb[t] - hsb + hhb) : 0.f;

        // two INDEPENDENT interleaved butterflies: v -> bsum, s -> sum of e
        float v = hsa + hsb;
        float s = ea + eb;
        v += __shfl_xor_sync(0xffffffffu, v, 16);  s += __shfl_xor_sync(0xffffffffu, s, 16);
        v += __shfl_xor_sync(0xffffffffu, v, 8);   s += __shfl_xor_sync(0xffffffffu, s, 8);
        v += __shfl_xor_sync(0xffffffffu, v, 4);   s += __shfl_xor_sync(0xffffffffu, s, 4);
        v += __shfl_xor_sync(0xffffffffu, v, 2);   s += __shfl_xor_sync(0xffffffffu, s, 2);
        v += __shfl_xor_sync(0xffffffffu, v, 1);   s += __shfl_xor_sync(0xffffffffu, s, 1);

        float ebb = expf(v);                             // exp(bsum), all lanes
        if (lane == 0) wr[t & 1][b] = ebb * s;           // batch rate sum
        __syncthreads();                                 // the only barrier per step

        const float4* w4 = (const float4*)wr[t & 1];
        float4 q0 = w4[0], q1 = w4[1], q2 = w4[2], q3 = w4[3];
        float tot = (((q0.x + q0.y) + (q0.z + q0.w)) + ((q1.x + q1.y) + (q1.z + q1.w)))
                  + (((q2.x + q2.y) + (q2.z + q2.w)) + ((q3.x + q3.y) + (q3.z + q3.w)));
        float thr = tot * (1.f / (BATCH * NNEUR));

        float sa = (ea * ebb > thr) ? 1.f : 0.f;
        float sb = (eb * ebb > thr) ? 1.f : 0.f;         // eb==0 -> never spikes (thr>0)
        cnta += sa;  cntb += sb;
        a0 = a1; a1 = a2; a2 = a3; a3 = sa;
        b0 = b1; b1 = b2; b2 = b3; b3 = sb;
    }
    out[b * NNEUR + lane] = cnta + log1pf(expf(-cnta));  // exact softplus, count>=0
    if (actb)
        out[b * NNEUR + lane + 32] = cntb + log1pf(expf(-cntb));
}

// =======================================================================================
extern "C" void kernel_launch(void* const* d_in, const int* in_sizes, int n_in,
                              void* d_out, int out_size) {
    const float* x    = (const float*)d_in[0];
    const float* fc_w = (const float*)d_in[1];
    const float* fc_b = (const float*)d_in[2];
    const float* lw   = (const float*)d_in[3];
    const float* hw   = (const float*)d_in[4];
    float* out = (float*)d_out;

    wT_kernel<<<(KDIM * NPAD + 255) / 256, 256>>>(fc_w);
    fused_kernel<<<dim3(NFRAMES / FT, NCHUNK), 256>>>(x);
    merge_kernel<<<(NFRAMES * NNEUR + 255) / 256, 256>>>(fc_b);
    scan_kernel<<<1, 512>>>(lw, hw, out);
    (void)in_sizes; (void)n_in; (void)out_size;
}